// round 12
// baseline (speedup 1.0000x reference)
#include <cuda_runtime.h>
#include <cuda_fp16.h>
#include <math.h>

// Problem constants (fixed by the dataset)
#define Cn   128
#define Hh   5
#define HC   (Hh*Cn)      // 640
#define MAXN 20000
#define MAXE 320000
#define MAXET (MAXE + MAXN)
#define EPSV 1e-16f
#define NEG_SLOPE 0.2f

// ---------------- scratch (static device globals) -----------------------------
__device__ __align__(16) __half g_h[(size_t)MAXN * HC];  // [N,H,C] fp16 (25.6 MB)
__device__ float g_asrc[MAXN * Hh];
__device__ float g_adst[MAXN * Hh];
__device__ float g_denom[MAXN * Hh];

// ---------------- tf32 TC GEMM (TBM=64), fused logits + balanced out-init ----
#define TBM  64
#define TBK  32
#define APAD 36
#define BPAD 132
#define CH2S 69
#define AS_BYTES (TBM * APAD * 4)               // 9216
#define BS_BYTES (TBK * BPAD * 4)               // 16896
#define SMEM_DYN (2 * AS_BYTES + 2 * BS_BYTES)  // 52224

__device__ __forceinline__ void cp16(unsigned dst, const void* src) {
    asm volatile("cp.async.cg.shared.global [%0], [%1], 16;"
                 :: "r"(dst), "l"(src));
}

__device__ __forceinline__ void mma_tf32(float d[4], const unsigned a[4],
                                         const unsigned b[2]) {
    asm volatile(
        "mma.sync.aligned.m16n8k8.row.col.f32.tf32.tf32.f32 "
        "{%0,%1,%2,%3}, {%4,%5,%6,%7}, {%8,%9}, {%0,%1,%2,%3};"
        : "+f"(d[0]), "+f"(d[1]), "+f"(d[2]), "+f"(d[3])
        : "r"(a[0]), "r"(a[1]), "r"(a[2]), "r"(a[3]), "r"(b[0]), "r"(b[1]));
}

__global__ __launch_bounds__(256, 3)
void gemm_tc_kernel(const float* __restrict__ A,
                    const float* __restrict__ B,
                    const float* __restrict__ att_src,
                    const float* __restrict__ att_dst,
                    const float* __restrict__ bias,
                    float* __restrict__ out,
                    int M) {
    extern __shared__ __align__(16) char smem_raw[];
    unsigned* Cs = (unsigned*)smem_raw;            // epilogue alias [64][69] half2

    const int tid    = threadIdx.x;
    const int head   = blockIdx.x;
    const int rowBlk = blockIdx.y * TBM;
    const int lane   = tid & 31;
    const int wid    = tid >> 5;
    const int warpM  = wid & 1;          // 0..1 -> 32 rows each
    const int warpN  = wid >> 1;         // 0..3 -> 32 cols each
    const int gid    = lane >> 2;
    const int tig    = lane & 3;

    float acc[2][4][4];
    #pragma unroll
    for (int m = 0; m < 2; m++)
        #pragma unroll
        for (int n = 0; n < 4; n++)
            #pragma unroll
            for (int r = 0; r < 4; r++) acc[m][n][r] = 0.0f;

    // load mappings: A 64x32 = 512 float4 (2/thread), B 32x128 = 1024 f4 (4/thread)
    const int bKrow  = tid >> 3;
    const int bF4    = tid & 7;
    const unsigned sbase = (unsigned)__cvta_generic_to_shared(smem_raw);
    const float* bpRow = B + (size_t)bKrow * HC + head * Cn;

    // prologue: chunk 0 -> stage 0
    {
        unsigned aB = sbase;
        unsigned bB = sbase + 2 * AS_BYTES;
        #pragma unroll
        for (int j = 0; j < 2; j++) {
            int idx  = tid + j * 256;
            int ar   = idx >> 3, af4 = idx & 7;
            int gR   = rowBlk + ar; if (gR >= M) gR = 0;
            cp16(aB + (ar * APAD + af4 * 4) * 4, A + (size_t)gR * Cn + af4 * 4);
        }
        #pragma unroll
        for (int j = 0; j < 4; j++) {
            int col = (bF4 + 8 * j) * 4;
            cp16(bB + (bKrow * BPAD + col) * 4, bpRow + col);
        }
        asm volatile("cp.async.commit_group;");
    }

    // balanced fused init: this block covers out rows [rowBlk, rowBlk+64),
    // head h handles float4 indices [h*2048/5, (h+1)*2048/5) of the 64x32 grid.
    {
        const float4* fp = (const float4*)(A + (size_t)rowBlk * Cn);
        const float4* bp = (const float4*)bias;
        float4*       op = (float4*)(out + (size_t)rowBlk * Cn);
        int start = (head * TBM * 32) / Hh;
        int end   = ((head + 1) * TBM * 32) / Hh;
        for (int idx = start + tid; idx < end; idx += 256) {
            int row = idx >> 5;
            if (rowBlk + row < M) {
                float4 v = fp[idx];
                float4 b = bp[idx & 31];
                v.x += b.x; v.y += b.y; v.z += b.z; v.w += b.w;
                op[idx] = v;
            }
        }
        if (tid < TBM) {
            int gRow = rowBlk + tid;
            if (gRow < M) g_denom[gRow * Hh + head] = 0.0f;
        }
    }

    #pragma unroll
    for (int c = 0; c < 4; c++) {
        if (c < 3) {
            int st = (c + 1) & 1;
            int kc = (c + 1) * TBK;
            unsigned aB = sbase + st * AS_BYTES;
            unsigned bB = sbase + 2 * AS_BYTES + st * BS_BYTES;
            #pragma unroll
            for (int j = 0; j < 2; j++) {
                int idx  = tid + j * 256;
                int ar   = idx >> 3, af4 = idx & 7;
                int gR   = rowBlk + ar; if (gR >= M) gR = 0;
                cp16(aB + (ar * APAD + af4 * 4) * 4,
                     A + (size_t)gR * Cn + kc + af4 * 4);
            }
            #pragma unroll
            for (int j = 0; j < 4; j++) {
                int col = (bF4 + 8 * j) * 4;
                cp16(bB + (bKrow * BPAD + col) * 4, bpRow + (size_t)kc * HC + col);
            }
            asm volatile("cp.async.commit_group;");
            asm volatile("cp.async.wait_group 1;");
        } else {
            asm volatile("cp.async.wait_group 0;");
        }
        __syncthreads();

        const float* Asp = (const float*)(smem_raw + (c & 1) * AS_BYTES);
        const float* Bsp = (const float*)(smem_raw + 2 * AS_BYTES + (c & 1) * BS_BYTES);

        #pragma unroll
        for (int kk = 0; kk < 4; kk++) {
            const int kb = kk * 8;
            unsigned a[2][4], b[4][2];
            #pragma unroll
            for (int m = 0; m < 2; m++) {
                int r0 = warpM * 32 + m * 16 + gid;
                a[m][0] = __float_as_uint(Asp[r0 * APAD + kb + tig]);
                a[m][1] = __float_as_uint(Asp[(r0 + 8) * APAD + kb + tig]);
                a[m][2] = __float_as_uint(Asp[r0 * APAD + kb + tig + 4]);
                a[m][3] = __float_as_uint(Asp[(r0 + 8) * APAD + kb + tig + 4]);
            }
            #pragma unroll
            for (int n = 0; n < 4; n++) {
                int cb = warpN * 32 + n * 8 + gid;
                b[n][0] = __float_as_uint(Bsp[(kb + tig) * BPAD + cb]);
                b[n][1] = __float_as_uint(Bsp[(kb + tig + 4) * BPAD + cb]);
            }
            #pragma unroll
            for (int m = 0; m < 2; m++)
                #pragma unroll
                for (int n = 0; n < 4; n++)
                    mma_tf32(acc[m][n], a[m], b[n]);
        }
        __syncthreads();
    }

    // epilogue: stage fp16 tile into Cs
    #pragma unroll
    for (int m = 0; m < 2; m++) {
        int r0 = warpM * 32 + m * 16 + gid;
        #pragma unroll
        for (int n = 0; n < 4; n++) {
            int ch = warpN * 16 + n * 4 + tig;
            __half2 h01 = __floats2half2_rn(acc[m][n][0], acc[m][n][1]);
            __half2 h23 = __floats2half2_rn(acc[m][n][2], acc[m][n][3]);
            Cs[r0 * CH2S + ch]       = *(unsigned*)&h01;
            Cs[(r0 + 8) * CH2S + ch] = *(unsigned*)&h23;
        }
    }
    __syncthreads();

    // fused attention logits: 4 lanes per row (row = tid>>2), shfl-reduce w=4
    {
        int row  = tid >> 2;          // 0..63
        int part = tid & 3;           // 16 half2 each
        int gRow = rowBlk + row;
        const float* asv = att_src + head * Cn;
        const float* adv = att_dst + head * Cn;
        float ps = 0.f, pd = 0.f;
        #pragma unroll
        for (int i = 0; i < 16; i++) {
            int ch = part * 16 + i;
            unsigned u = Cs[row * CH2S + ch];
            float2 f = __half22float2(*(__half2*)&u);
            ps = fmaf(f.x, __ldg(asv + 2 * ch), ps);
            ps = fmaf(f.y, __ldg(asv + 2 * ch + 1), ps);
            pd = fmaf(f.x, __ldg(adv + 2 * ch), pd);
            pd = fmaf(f.y, __ldg(adv + 2 * ch + 1), pd);
        }
        ps += __shfl_xor_sync(0xffffffffu, ps, 1, 4);
        ps += __shfl_xor_sync(0xffffffffu, ps, 2, 4);
        pd += __shfl_xor_sync(0xffffffffu, pd, 1, 4);
        pd += __shfl_xor_sync(0xffffffffu, pd, 2, 4);
        if (part == 0 && gRow < M) {
            g_asrc[gRow * Hh + head] = ps;
            g_adst[gRow * Hh + head] = pd;
        }
    }

    // coalesced fp16 store to g_h: 64 rows x 64 half2 = 4096 words
    unsigned* gh = (unsigned*)g_h;
    #pragma unroll
    for (int i = 0; i < 16; i++) {
        int idx  = i * 256 + tid;
        int row  = idx >> 6;
        int ch   = idx & 63;
        int gRow = rowBlk + row;
        if (gRow < M)
            gh[(size_t)gRow * (HC / 2) + head * 64 + ch] = Cs[row * CH2S + ch];
    }
}

// ---------------- kernel 2: softmax denominators (no max pass) ---------------
__global__ void denom_kernel(const int* __restrict__ ei, int E, int Etot) {
    int e = blockIdx.x * blockDim.x + threadIdx.x;
    if (e >= Etot) return;
    int src, dst;
    if (e < E) { src = ei[e]; dst = ei[E + e]; }
    else       { src = e - E; dst = src; }
    #pragma unroll
    for (int h = 0; h < Hh; h++) {
        float v = g_asrc[src * Hh + h] + g_adst[dst * Hh + h];
        v = v > 0.f ? v : NEG_SLOPE * v;
        atomicAdd(&g_denom[dst * Hh + h], __expf(v));
    }
}

// ---------------- helper: accumulate 4 fp16 channels of one head -------------
__device__ __forceinline__ void acc_head(float4& acc4, uint2 u, float wgt) {
    float2 lo = __half22float2(*(const __half2*)&u.x);
    float2 hi = __half22float2(*(const __half2*)&u.y);
    acc4.x = fmaf(wgt, lo.x, acc4.x);
    acc4.y = fmaf(wgt, lo.y, acc4.y);
    acc4.z = fmaf(wgt, hi.x, acc4.z);
    acc4.w = fmaf(wgt, hi.y, acc4.w);
}

// ---------------- kernel 3: weighted scatter, warp per edge, fp16 h ----------
__global__ __launch_bounds__(256)
void scatter_kernel(const int* __restrict__ ei,
                    float* __restrict__ out, int E, int Etot) {
    int e = blockIdx.x * (blockDim.x >> 5) + (threadIdx.x >> 5);
    if (e >= Etot) return;
    int lane = threadIdx.x & 31;

    int src, dst;
    if (e < E) { src = ei[e]; dst = ei[E + e]; }
    else       { src = e - E; dst = src; }

    float wv = 0.f;
    if (lane < Hh) {
        float v = g_asrc[src * Hh + lane] + g_adst[dst * Hh + lane];
        v = v > 0.f ? v : NEG_SLOPE * v;
        wv = __expf(v) / (g_denom[dst * Hh + lane] + EPSV) * (1.0f / Hh);
    }
    float w0 = __shfl_sync(0xffffffffu, wv, 0);
    float w1 = __shfl_sync(0xffffffffu, wv, 1);
    float w2 = __shfl_sync(0xffffffffu, wv, 2);
    float w3 = __shfl_sync(0xffffffffu, wv, 3);
    float w4 = __shfl_sync(0xffffffffu, wv, 4);

    const uint2* hp = (const uint2*)(g_h + (size_t)src * HC) + lane;
    uint2 u0 = hp[0 * 32];
    uint2 u1 = hp[1 * 32];
    uint2 u2 = hp[2 * 32];
    uint2 u3 = hp[3 * 32];
    uint2 u4 = hp[4 * 32];

    float4 a = make_float4(0.f, 0.f, 0.f, 0.f);
    acc_head(a, u0, w0);
    acc_head(a, u1, w1);
    acc_head(a, u2, w2);
    acc_head(a, u3, w3);
    acc_head(a, u4, w4);

    float* op = out + (size_t)dst * Cn + lane * 4;
    asm volatile("red.global.add.v4.f32 [%0], {%1, %2, %3, %4};"
                 :: "l"(op), "f"(a.x), "f"(a.y), "f"(a.z), "f"(a.w)
                 : "memory");
}

// ---------------- launch -------------------------------------------------------
extern "C" void kernel_launch(void* const* d_in, const int* in_sizes, int n_in,
                              void* d_out, int out_size) {
    const float* features = (const float*)d_in[0];
    const float* W        = (const float*)d_in[1];
    const float* att_src  = (const float*)d_in[2];
    const float* att_dst  = (const float*)d_in[3];
    const float* bias     = (const float*)d_in[4];
    const int*   ei       = (const int*)d_in[5];
    float*       out      = (float*)d_out;

    const int Nn   = in_sizes[0] / Cn;   // 20000
    const int E    = in_sizes[5] / 2;    // 320000
    const int Etot = E + Nn;             // 340000

    // 1) GEMM (tf32 TC, pipelined, TBM=64) + fused logits + balanced init
    {
        cudaFuncSetAttribute(gemm_tc_kernel,
                             cudaFuncAttributeMaxDynamicSharedMemorySize, SMEM_DYN);
        dim3 grid(Hh, (Nn + TBM - 1) / TBM);   // (5, 313)
        gemm_tc_kernel<<<grid, 256, SMEM_DYN>>>(features, W, att_src, att_dst,
                                                bias, out, Nn);
    }

    // 2) softmax denominators
    denom_kernel<<<(Etot + 255) / 256, 256>>>(ei, E, Etot);

    // 3) weighted scatter (8 edges per 256-thread block)
    scatter_kernel<<<(Etot + 7) / 8, 256>>>(ei, out, E, Etot);
}

// round 13
// speedup vs baseline: 1.1066x; 1.1066x over previous
#include <cuda_runtime.h>
#include <cuda_fp16.h>
#include <math.h>

// Problem constants (fixed by the dataset)
#define Cn   128
#define Hh   5
#define HC   (Hh*Cn)      // 640
#define MAXN 20000
#define MAXE 320000
#define MAXET (MAXE + MAXN)
#define EPSV 1e-16f
#define NEG_SLOPE 0.2f

// ---------------- scratch (static device globals) -----------------------------
__device__ __align__(16) __half g_h[(size_t)MAXN * HC];   // [N,H,C] fp16 (25.6 MB)
__device__ __align__(16) __half g_fh[(size_t)MAXN * Cn];  // features fp16 (5.1 MB)
__device__ __align__(16) __half g_wt[HC * Cn];            // W^T fp16 [n][k] (164 KB)
__device__ float g_asrc[MAXN * Hh];
__device__ float g_adst[MAXN * Hh];
__device__ float g_denom[MAXN * Hh];

// ---------------- kernel 0: prep — out init, fp16 converts, denom zero --------
__global__ void prep_kernel(const float* __restrict__ features,
                            const float* __restrict__ W,
                            const float* __restrict__ bias,
                            float* __restrict__ out, int Nn) {
    int i = blockIdx.x * blockDim.x + threadIdx.x;
    int NC = Nn * Cn;
    if (i < NC) {
        float f = features[i];
        out[i]  = f + bias[i & (Cn - 1)];
        g_fh[i] = __float2half_rn(f);
    }
    if (i < HC * Cn) {                       // W^T: g_wt[n][k] = W[k][n]
        int n = i >> 7, k = i & (Cn - 1);
        g_wt[i] = __float2half_rn(W[(size_t)k * HC + n]);
    }
    if (i < Nn * Hh) g_denom[i] = 0.0f;
}

// ---------------- fp16 TC GEMM, un-chunked K + fused logits -------------------
#define TBM   64
#define AWPAD 68            // A smem row stride in 32-bit words (= 272 B)
#define BWPAD 68            // B smem row stride in words
#define CH2S  69
#define AS_WORDS (TBM * AWPAD)          // 4352 words = 17408 B
#define BS_WORDS (Cn  * BWPAD)          // 8704 words = 34816 B
#define SMEM_DYN ((AS_WORDS + BS_WORDS) * 4)   // 52224 B

__device__ __forceinline__ void cp16(unsigned dst, const void* src) {
    asm volatile("cp.async.cg.shared.global [%0], [%1], 16;"
                 :: "r"(dst), "l"(src));
}

__device__ __forceinline__ void mma_f16(float d[4], const unsigned a[4],
                                        const unsigned b[2]) {
    asm volatile(
        "mma.sync.aligned.m16n8k16.row.col.f32.f16.f16.f32 "
        "{%0,%1,%2,%3}, {%4,%5,%6,%7}, {%8,%9}, {%0,%1,%2,%3};"
        : "+f"(d[0]), "+f"(d[1]), "+f"(d[2]), "+f"(d[3])
        : "r"(a[0]), "r"(a[1]), "r"(a[2]), "r"(a[3]), "r"(b[0]), "r"(b[1]));
}

__global__ __launch_bounds__(256, 3)
void gemm_tc_kernel(const float* __restrict__ att_src,
                    const float* __restrict__ att_dst,
                    int M) {
    extern __shared__ __align__(16) char smem_raw[];
    unsigned* As = (unsigned*)smem_raw;                    // [64][68] words (half2)
    unsigned* Bs = (unsigned*)smem_raw + AS_WORDS;         // [128][68] words
    unsigned* Cs = (unsigned*)smem_raw;                    // epilogue alias [64][69]

    const int tid    = threadIdx.x;
    const int head   = blockIdx.x;
    const int rowBlk = blockIdx.y * TBM;
    const int lane   = tid & 31;
    const int wid    = tid >> 5;
    const int warpM  = wid & 1;          // 32 rows each
    const int warpN  = wid >> 1;         // 32 cols each
    const int gid    = lane >> 2;
    const int tig    = lane & 3;

    const unsigned sbase = (unsigned)__cvta_generic_to_shared(smem_raw);

    // ---- load A (64x128 fp16) and B (128x128 fp16 = W^T slab) via cp.async ----
    // A: 64 rows x 16 groups of 16B; 1024 groups, 4/thread
    #pragma unroll
    for (int j = 0; j < 4; j++) {
        int idx = tid + j * 256;
        int r = idx >> 4, c = idx & 15;
        int gR = rowBlk + r; if (gR >= M) gR = 0;
        cp16(sbase + (r * AWPAD + c * 4) * 4,
             g_fh + (size_t)gR * Cn + c * 8);
    }
    // B: 128 rows (n) x 16 groups; 2048 groups, 8/thread
    #pragma unroll
    for (int j = 0; j < 8; j++) {
        int idx = tid + j * 256;
        int r = idx >> 4, c = idx & 15;
        cp16(sbase + (AS_WORDS + r * BWPAD + c * 4) * 4,
             g_wt + (size_t)(head * Cn + r) * Cn + c * 8);
    }
    asm volatile("cp.async.commit_group;");
    asm volatile("cp.async.wait_group 0;");
    __syncthreads();

    float acc[2][4][4];
    #pragma unroll
    for (int m = 0; m < 2; m++)
        #pragma unroll
        for (int n = 0; n < 4; n++)
            #pragma unroll
            for (int r = 0; r < 4; r++) acc[m][n][r] = 0.0f;

    // ---- mainloop: 8 k-steps of m16n8k16 ----
    #pragma unroll
    for (int ks = 0; ks < 8; ks++) {
        const int kw = ks * 8 + tig;       // half2 word offset within row
        unsigned a[2][4], b[4][2];
        #pragma unroll
        for (int m = 0; m < 2; m++) {
            int r0 = warpM * 32 + m * 16 + gid;
            a[m][0] = As[r0 * AWPAD + kw];
            a[m][1] = As[(r0 + 8) * AWPAD + kw];
            a[m][2] = As[r0 * AWPAD + kw + 4];
            a[m][3] = As[(r0 + 8) * AWPAD + kw + 4];
        }
        #pragma unroll
        for (int n = 0; n < 4; n++) {
            int cb = warpN * 32 + n * 8 + gid;
            b[n][0] = Bs[cb * BWPAD + kw];
            b[n][1] = Bs[cb * BWPAD + kw + 4];
        }
        #pragma unroll
        for (int m = 0; m < 2; m++)
            #pragma unroll
            for (int n = 0; n < 4; n++)
                mma_f16(acc[m][n], a[m], b[n]);
    }
    __syncthreads();

    // ---- epilogue: stage fp16 tile into Cs (aliases As/Bs) ----
    #pragma unroll
    for (int m = 0; m < 2; m++) {
        int r0 = warpM * 32 + m * 16 + gid;
        #pragma unroll
        for (int n = 0; n < 4; n++) {
            int ch = warpN * 16 + n * 4 + tig;
            __half2 h01 = __floats2half2_rn(acc[m][n][0], acc[m][n][1]);
            __half2 h23 = __floats2half2_rn(acc[m][n][2], acc[m][n][3]);
            Cs[r0 * CH2S + ch]       = *(unsigned*)&h01;
            Cs[(r0 + 8) * CH2S + ch] = *(unsigned*)&h23;
        }
    }
    __syncthreads();

    // fused attention logits: 4 lanes per row, shfl-reduce width 4
    {
        int row  = tid >> 2;          // 0..63
        int part = tid & 3;
        int gRow = rowBlk + row;
        const float* asv = att_src + head * Cn;
        const float* adv = att_dst + head * Cn;
        float ps = 0.f, pd = 0.f;
        #pragma unroll
        for (int i = 0; i < 16; i++) {
            int ch = part * 16 + i;
            unsigned u = Cs[row * CH2S + ch];
            float2 f = __half22float2(*(__half2*)&u);
            ps = fmaf(f.x, __ldg(asv + 2 * ch), ps);
            ps = fmaf(f.y, __ldg(asv + 2 * ch + 1), ps);
            pd = fmaf(f.x, __ldg(adv + 2 * ch), pd);
            pd = fmaf(f.y, __ldg(adv + 2 * ch + 1), pd);
        }
        ps += __shfl_xor_sync(0xffffffffu, ps, 1, 4);
        ps += __shfl_xor_sync(0xffffffffu, ps, 2, 4);
        pd += __shfl_xor_sync(0xffffffffu, pd, 1, 4);
        pd += __shfl_xor_sync(0xffffffffu, pd, 2, 4);
        if (part == 0 && gRow < M) {
            g_asrc[gRow * Hh + head] = ps;
            g_adst[gRow * Hh + head] = pd;
        }
    }

    // coalesced fp16 store to g_h
    unsigned* gh = (unsigned*)g_h;
    #pragma unroll
    for (int i = 0; i < 16; i++) {
        int idx  = i * 256 + tid;
        int row  = idx >> 6;
        int ch   = idx & 63;
        int gRow = rowBlk + row;
        if (gRow < M)
            gh[(size_t)gRow * (HC / 2) + head * 64 + ch] = Cs[row * CH2S + ch];
    }
}

// ---------------- kernel 2: softmax denominators (no max pass) ---------------
__global__ void denom_kernel(const int* __restrict__ ei, int E, int Etot) {
    int e = blockIdx.x * blockDim.x + threadIdx.x;
    if (e >= Etot) return;
    int src, dst;
    if (e < E) { src = ei[e]; dst = ei[E + e]; }
    else       { src = e - E; dst = src; }
    #pragma unroll
    for (int h = 0; h < Hh; h++) {
        float v = g_asrc[src * Hh + h] + g_adst[dst * Hh + h];
        v = v > 0.f ? v : NEG_SLOPE * v;
        atomicAdd(&g_denom[dst * Hh + h], __expf(v));
    }
}

// ---------------- helper: accumulate 4 fp16 channels of one head -------------
__device__ __forceinline__ void acc_head(float4& acc4, uint2 u, float wgt) {
    float2 lo = __half22float2(*(const __half2*)&u.x);
    float2 hi = __half22float2(*(const __half2*)&u.y);
    acc4.x = fmaf(wgt, lo.x, acc4.x);
    acc4.y = fmaf(wgt, lo.y, acc4.y);
    acc4.z = fmaf(wgt, hi.x, acc4.z);
    acc4.w = fmaf(wgt, hi.y, acc4.w);
}

// ---------------- kernel 3: weighted scatter, warp per edge, fp16 h ----------
__global__ __launch_bounds__(256)
void scatter_kernel(const int* __restrict__ ei,
                    float* __restrict__ out, int E, int Etot) {
    int e = blockIdx.x * (blockDim.x >> 5) + (threadIdx.x >> 5);
    if (e >= Etot) return;
    int lane = threadIdx.x & 31;

    int src, dst;
    if (e < E) { src = ei[e]; dst = ei[E + e]; }
    else       { src = e - E; dst = src; }

    float wv = 0.f;
    if (lane < Hh) {
        float v = g_asrc[src * Hh + lane] + g_adst[dst * Hh + lane];
        v = v > 0.f ? v : NEG_SLOPE * v;
        wv = __expf(v) / (g_denom[dst * Hh + lane] + EPSV) * (1.0f / Hh);
    }
    float w0 = __shfl_sync(0xffffffffu, wv, 0);
    float w1 = __shfl_sync(0xffffffffu, wv, 1);
    float w2 = __shfl_sync(0xffffffffu, wv, 2);
    float w3 = __shfl_sync(0xffffffffu, wv, 3);
    float w4 = __shfl_sync(0xffffffffu, wv, 4);

    const uint2* hp = (const uint2*)(g_h + (size_t)src * HC) + lane;
    uint2 u0 = hp[0 * 32];
    uint2 u1 = hp[1 * 32];
    uint2 u2 = hp[2 * 32];
    uint2 u3 = hp[3 * 32];
    uint2 u4 = hp[4 * 32];

    float4 a = make_float4(0.f, 0.f, 0.f, 0.f);
    acc_head(a, u0, w0);
    acc_head(a, u1, w1);
    acc_head(a, u2, w2);
    acc_head(a, u3, w3);
    acc_head(a, u4, w4);

    float* op = out + (size_t)dst * Cn + lane * 4;
    asm volatile("red.global.add.v4.f32 [%0], {%1, %2, %3, %4};"
                 :: "l"(op), "f"(a.x), "f"(a.y), "f"(a.z), "f"(a.w)
                 : "memory");
}

// ---------------- launch -------------------------------------------------------
extern "C" void kernel_launch(void* const* d_in, const int* in_sizes, int n_in,
                              void* d_out, int out_size) {
    const float* features = (const float*)d_in[0];
    const float* W        = (const float*)d_in[1];
    const float* att_src  = (const float*)d_in[2];
    const float* att_dst  = (const float*)d_in[3];
    const float* bias     = (const float*)d_in[4];
    const int*   ei       = (const int*)d_in[5];
    float*       out      = (float*)d_out;

    const int Nn   = in_sizes[0] / Cn;   // 20000
    const int E    = in_sizes[5] / 2;    // 320000
    const int Etot = E + Nn;             // 340000

    // 0) prep: out = features + bias, fp16 converts, denom zero
    prep_kernel<<<(Nn * Cn + 255) / 256, 256>>>(features, W, bias, out, Nn);

    // 1) GEMM (fp16 TC, un-chunked K) + fused logits
    {
        cudaFuncSetAttribute(gemm_tc_kernel,
                             cudaFuncAttributeMaxDynamicSharedMemorySize, SMEM_DYN);
        dim3 grid(Hh, (Nn + TBM - 1) / TBM);   // (5, 313)
        gemm_tc_kernel<<<grid, 256, SMEM_DYN>>>(att_src, att_dst, Nn);
    }

    // 2) softmax denominators
    denom_kernel<<<(Etot + 255) / 256, 256>>>(ei, E, Etot);

    // 3) weighted scatter (8 edges per 256-thread block)
    scatter_kernel<<<(Etot + 7) / 8, 256>>>(ei, out, E, Etot);
}

// round 14
// speedup vs baseline: 1.2200x; 1.1025x over previous
#include <cuda_runtime.h>
#include <cuda_fp16.h>
#include <math.h>

// Problem constants (fixed by the dataset)
#define Cn   128
#define Hh   5
#define NPAD 8            // per-node stride for (asrc/adst/denom): 32 B, v4-aligned
#define HC   (Hh*Cn)      // 640
#define MAXN 20000
#define MAXE 320000
#define MAXET (MAXE + MAXN)
#define EPSV 1e-16f
#define NEG_SLOPE 0.2f

// ---------------- scratch (static device globals) -----------------------------
__device__ __align__(16) __half g_h[(size_t)MAXN * HC];   // [N,H,C] fp16 (25.6 MB)
__device__ __align__(16) __half g_fh[(size_t)MAXN * Cn];  // features fp16 (5.1 MB)
__device__ __align__(16) __half g_wt[HC * Cn];            // W^T fp16 [n][k]
__device__ __align__(16) float g_asrc[MAXN * NPAD];
__device__ __align__(16) float g_adst[MAXN * NPAD];
__device__ __align__(16) float g_denom[MAXN * NPAD];

// ---------------- kernel 0: prep — out init, fp16 converts, denom zero --------
__global__ void prep_kernel(const float* __restrict__ features,
                            const float* __restrict__ W,
                            const float* __restrict__ bias,
                            float* __restrict__ out, int Nn) {
    int i = blockIdx.x * blockDim.x + threadIdx.x;
    int NC = Nn * Cn;
    if (i < NC) {
        float f = features[i];
        out[i]  = f + bias[i & (Cn - 1)];
        g_fh[i] = __float2half_rn(f);
    }
    if (i < HC * Cn) {                       // W^T: g_wt[n][k] = W[k][n]
        int n = i >> 7, k = i & (Cn - 1);
        g_wt[i] = __float2half_rn(W[(size_t)k * HC + n]);
    }
    if (i < Nn * NPAD) g_denom[i] = 0.0f;
}

// ---------------- fp16 TC GEMM, un-chunked K + fused logits -------------------
#define TBM   64
#define AWPAD 68
#define BWPAD 68
#define CH2S  69
#define AS_WORDS (TBM * AWPAD)
#define BS_WORDS (Cn  * BWPAD)
#define SMEM_DYN ((AS_WORDS + BS_WORDS) * 4)   // 52224 B

__device__ __forceinline__ void cp16(unsigned dst, const void* src) {
    asm volatile("cp.async.cg.shared.global [%0], [%1], 16;"
                 :: "r"(dst), "l"(src));
}

__device__ __forceinline__ void mma_f16(float d[4], const unsigned a[4],
                                        const unsigned b[2]) {
    asm volatile(
        "mma.sync.aligned.m16n8k16.row.col.f32.f16.f16.f32 "
        "{%0,%1,%2,%3}, {%4,%5,%6,%7}, {%8,%9}, {%0,%1,%2,%3};"
        : "+f"(d[0]), "+f"(d[1]), "+f"(d[2]), "+f"(d[3])
        : "r"(a[0]), "r"(a[1]), "r"(a[2]), "r"(a[3]), "r"(b[0]), "r"(b[1]));
}

__global__ __launch_bounds__(256, 3)
void gemm_tc_kernel(const float* __restrict__ att_src,
                    const float* __restrict__ att_dst,
                    int M) {
    extern __shared__ __align__(16) char smem_raw[];
    unsigned* As = (unsigned*)smem_raw;
    unsigned* Bs = (unsigned*)smem_raw + AS_WORDS;
    unsigned* Cs = (unsigned*)smem_raw;            // epilogue alias

    const int tid    = threadIdx.x;
    const int head   = blockIdx.x;
    const int rowBlk = blockIdx.y * TBM;
    const int lane   = tid & 31;
    const int wid    = tid >> 5;
    const int warpM  = wid & 1;
    const int warpN  = wid >> 1;
    const int gid    = lane >> 2;
    const int tig    = lane & 3;

    const unsigned sbase = (unsigned)__cvta_generic_to_shared(smem_raw);

    #pragma unroll
    for (int j = 0; j < 4; j++) {
        int idx = tid + j * 256;
        int r = idx >> 4, c = idx & 15;
        int gR = rowBlk + r; if (gR >= M) gR = 0;
        cp16(sbase + (r * AWPAD + c * 4) * 4, g_fh + (size_t)gR * Cn + c * 8);
    }
    #pragma unroll
    for (int j = 0; j < 8; j++) {
        int idx = tid + j * 256;
        int r = idx >> 4, c = idx & 15;
        cp16(sbase + (AS_WORDS + r * BWPAD + c * 4) * 4,
             g_wt + (size_t)(head * Cn + r) * Cn + c * 8);
    }
    asm volatile("cp.async.commit_group;");
    asm volatile("cp.async.wait_group 0;");
    __syncthreads();

    float acc[2][4][4];
    #pragma unroll
    for (int m = 0; m < 2; m++)
        #pragma unroll
        for (int n = 0; n < 4; n++)
            #pragma unroll
            for (int r = 0; r < 4; r++) acc[m][n][r] = 0.0f;

    #pragma unroll
    for (int ks = 0; ks < 8; ks++) {
        const int kw = ks * 8 + tig;
        unsigned a[2][4], b[4][2];
        #pragma unroll
        for (int m = 0; m < 2; m++) {
            int r0 = warpM * 32 + m * 16 + gid;
            a[m][0] = As[r0 * AWPAD + kw];
            a[m][1] = As[(r0 + 8) * AWPAD + kw];
            a[m][2] = As[r0 * AWPAD + kw + 4];
            a[m][3] = As[(r0 + 8) * AWPAD + kw + 4];
        }
        #pragma unroll
        for (int n = 0; n < 4; n++) {
            int cb = warpN * 32 + n * 8 + gid;
            b[n][0] = Bs[cb * BWPAD + kw];
            b[n][1] = Bs[cb * BWPAD + kw + 4];
        }
        #pragma unroll
        for (int m = 0; m < 2; m++)
            #pragma unroll
            for (int n = 0; n < 4; n++)
                mma_f16(acc[m][n], a[m], b[n]);
    }
    __syncthreads();

    #pragma unroll
    for (int m = 0; m < 2; m++) {
        int r0 = warpM * 32 + m * 16 + gid;
        #pragma unroll
        for (int n = 0; n < 4; n++) {
            int ch = warpN * 16 + n * 4 + tig;
            __half2 h01 = __floats2half2_rn(acc[m][n][0], acc[m][n][1]);
            __half2 h23 = __floats2half2_rn(acc[m][n][2], acc[m][n][3]);
            Cs[r0 * CH2S + ch]       = *(unsigned*)&h01;
            Cs[(r0 + 8) * CH2S + ch] = *(unsigned*)&h23;
        }
    }
    __syncthreads();

    // fused attention logits: 4 lanes per row, shfl-reduce width 4
    {
        int row  = tid >> 2;
        int part = tid & 3;
        int gRow = rowBlk + row;
        const float* asv = att_src + head * Cn;
        const float* adv = att_dst + head * Cn;
        float ps = 0.f, pd = 0.f;
        #pragma unroll
        for (int i = 0; i < 16; i++) {
            int ch = part * 16 + i;
            unsigned u = Cs[row * CH2S + ch];
            float2 f = __half22float2(*(__half2*)&u);
            ps = fmaf(f.x, __ldg(asv + 2 * ch), ps);
            ps = fmaf(f.y, __ldg(asv + 2 * ch + 1), ps);
            pd = fmaf(f.x, __ldg(adv + 2 * ch), pd);
            pd = fmaf(f.y, __ldg(adv + 2 * ch + 1), pd);
        }
        ps += __shfl_xor_sync(0xffffffffu, ps, 1, 4);
        ps += __shfl_xor_sync(0xffffffffu, ps, 2, 4);
        pd += __shfl_xor_sync(0xffffffffu, pd, 1, 4);
        pd += __shfl_xor_sync(0xffffffffu, pd, 2, 4);
        if (part == 0 && gRow < M) {
            g_asrc[gRow * NPAD + head] = ps;
            g_adst[gRow * NPAD + head] = pd;
        }
    }

    // coalesced fp16 store to g_h
    unsigned* gh = (unsigned*)g_h;
    #pragma unroll
    for (int i = 0; i < 16; i++) {
        int idx  = i * 256 + tid;
        int row  = idx >> 6;
        int ch   = idx & 63;
        int gRow = rowBlk + row;
        if (gRow < M)
            gh[(size_t)gRow * (HC / 2) + head * 64 + ch] = Cs[row * CH2S + ch];
    }
}

// ---------------- kernel 2: softmax denominators, vectorized ------------------
__global__ void denom_kernel(const int* __restrict__ ei, int E, int Etot) {
    int e = blockIdx.x * blockDim.x + threadIdx.x;
    if (e >= Etot) return;
    int src, dst;
    if (e < E) { src = ei[e]; dst = ei[E + e]; }
    else       { src = e - E; dst = src; }

    float4 s4 = __ldg((const float4*)(g_asrc + src * NPAD));
    float  s5 = __ldg(g_asrc + src * NPAD + 4);
    float4 d4 = __ldg((const float4*)(g_adst + dst * NPAD));
    float  d5 = __ldg(g_adst + dst * NPAD + 4);

    float v0 = s4.x + d4.x, v1 = s4.y + d4.y, v2 = s4.z + d4.z,
          v3 = s4.w + d4.w, v4 = s5 + d5;
    v0 = v0 > 0.f ? v0 : NEG_SLOPE * v0;
    v1 = v1 > 0.f ? v1 : NEG_SLOPE * v1;
    v2 = v2 > 0.f ? v2 : NEG_SLOPE * v2;
    v3 = v3 > 0.f ? v3 : NEG_SLOPE * v3;
    v4 = v4 > 0.f ? v4 : NEG_SLOPE * v4;
    float t0 = __expf(v0), t1 = __expf(v1), t2 = __expf(v2),
          t3 = __expf(v3), t4 = __expf(v4);

    float* dp = g_denom + dst * NPAD;             // 32 B aligned
    asm volatile("red.global.add.v4.f32 [%0], {%1, %2, %3, %4};"
                 :: "l"(dp), "f"(t0), "f"(t1), "f"(t2), "f"(t3) : "memory");
    asm volatile("red.global.add.f32 [%0], %1;"
                 :: "l"(dp + 4), "f"(t4) : "memory");
}

// ---------------- helper: accumulate 4 fp16 channels of one head -------------
__device__ __forceinline__ void acc_head(float4& acc4, uint2 u, float wgt) {
    float2 lo = __half22float2(*(const __half2*)&u.x);
    float2 hi = __half22float2(*(const __half2*)&u.y);
    acc4.x = fmaf(wgt, lo.x, acc4.x);
    acc4.y = fmaf(wgt, lo.y, acc4.y);
    acc4.z = fmaf(wgt, hi.x, acc4.z);
    acc4.w = fmaf(wgt, hi.y, acc4.w);
}

// ---------------- kernel 3: weighted scatter, warp per edge, fp16 h ----------
__global__ __launch_bounds__(256)
void scatter_kernel(const int* __restrict__ ei,
                    float* __restrict__ out, int E, int Etot) {
    int e = blockIdx.x * (blockDim.x >> 5) + (threadIdx.x >> 5);
    if (e >= Etot) return;
    int lane = threadIdx.x & 31;

    int src, dst;
    if (e < E) { src = ei[e]; dst = ei[E + e]; }
    else       { src = e - E; dst = src; }

    float wv = 0.f;
    if (lane < Hh) {
        float v = g_asrc[src * NPAD + lane] + g_adst[dst * NPAD + lane];
        v = v > 0.f ? v : NEG_SLOPE * v;
        wv = __expf(v) / (g_denom[dst * NPAD + lane] + EPSV) * (1.0f / Hh);
    }
    float w0 = __shfl_sync(0xffffffffu, wv, 0);
    float w1 = __shfl_sync(0xffffffffu, wv, 1);
    float w2 = __shfl_sync(0xffffffffu, wv, 2);
    float w3 = __shfl_sync(0xffffffffu, wv, 3);
    float w4 = __shfl_sync(0xffffffffu, wv, 4);

    const uint2* hp = (const uint2*)(g_h + (size_t)src * HC) + lane;
    uint2 u0 = hp[0 * 32];
    uint2 u1 = hp[1 * 32];
    uint2 u2 = hp[2 * 32];
    uint2 u3 = hp[3 * 32];
    uint2 u4 = hp[4 * 32];

    float4 a = make_float4(0.f, 0.f, 0.f, 0.f);
    acc_head(a, u0, w0);
    acc_head(a, u1, w1);
    acc_head(a, u2, w2);
    acc_head(a, u3, w3);
    acc_head(a, u4, w4);

    float* op = out + (size_t)dst * Cn + lane * 4;
    asm volatile("red.global.add.v4.f32 [%0], {%1, %2, %3, %4};"
                 :: "l"(op), "f"(a.x), "f"(a.y), "f"(a.z), "f"(a.w)
                 : "memory");
}

// ---------------- launch -------------------------------------------------------
extern "C" void kernel_launch(void* const* d_in, const int* in_sizes, int n_in,
                              void* d_out, int out_size) {
    const float* features = (const float*)d_in[0];
    const float* W        = (const float*)d_in[1];
    const float* att_src  = (const float*)d_in[2];
    const float* att_dst  = (const float*)d_in[3];
    const float* bias     = (const float*)d_in[4];
    const int*   ei       = (const int*)d_in[5];
    float*       out      = (float*)d_out;

    const int Nn   = in_sizes[0] / Cn;   // 20000
    const int E    = in_sizes[5] / 2;    // 320000
    const int Etot = E + Nn;             // 340000

    // 0) prep: out = features + bias, fp16 converts, denom zero (padded)
    prep_kernel<<<(Nn * Cn + 255) / 256, 256>>>(features, W, bias, out, Nn);

    // 1) GEMM (fp16 TC, un-chunked K) + fused logits
    {
        cudaFuncSetAttribute(gemm_tc_kernel,
                             cudaFuncAttributeMaxDynamicSharedMemorySize, SMEM_DYN);
        dim3 grid(Hh, (Nn + TBM - 1) / TBM);   // (5, 313)
        gemm_tc_kernel<<<grid, 256, SMEM_DYN>>>(att_src, att_dst, Nn);
    }

    // 2) softmax denominators (vectorized loads + v4 atomics)
    denom_kernel<<<(Etot + 255) / 256, 256>>>(ei, E, Etot);

    // 3) weighted scatter (8 edges per 256-thread block)
    scatter_kernel<<<(Etot + 7) / 8, 256>>>(ei, out, E, Etot);
}

// round 15
// speedup vs baseline: 1.2671x; 1.0386x over previous
#include <cuda_runtime.h>
#include <cuda_fp16.h>
#include <math.h>

// Problem constants (fixed by the dataset)
#define Cn   128
#define Hh   5
#define NPAD 8            // per-node stride for (asrc/adst/denom): 32 B, v4-aligned
#define HC   (Hh*Cn)      // 640
#define MAXN 20000
#define MAXE 320000
#define MAXET (MAXE + MAXN)
#define EPSV 1e-16f
#define NEG_SLOPE 0.2f

// ---------------- scratch (static device globals) -----------------------------
__device__ __align__(16) __half g_h[(size_t)MAXN * HC];   // [N,H,C] fp16 (25.6 MB)
__device__ __align__(16) __half g_fh[(size_t)MAXN * Cn];  // features fp16 (5.1 MB)
__device__ __align__(16) __half g_wt[HC * Cn];            // W^T fp16 [n][k]
__device__ __align__(16) float g_asrc[MAXN * NPAD];
__device__ __align__(16) float g_adst[MAXN * NPAD];
__device__ __align__(16) float g_denom[MAXN * NPAD];

// ---------------- kernel 0: prep (vectorized) ---------------------------------
__global__ void prep_kernel(const float4* __restrict__ features4,
                            const float*  __restrict__ W,
                            const float4* __restrict__ bias4,
                            float4* __restrict__ out4, int Nn) {
    int i = blockIdx.x * blockDim.x + threadIdx.x;
    int NC4 = Nn * (Cn / 4);                    // 640000
    if (i < NC4) {
        float4 f = features4[i];
        float4 b = bias4[i & 31];
        out4[i] = make_float4(f.x + b.x, f.y + b.y, f.z + b.z, f.w + b.w);
        __half2 h01 = __floats2half2_rn(f.x, f.y);
        __half2 h23 = __floats2half2_rn(f.z, f.w);
        uint2 pk; pk.x = *(unsigned*)&h01; pk.y = *(unsigned*)&h23;
        ((uint2*)g_fh)[i] = pk;
    }
    if (i < HC * (Cn / 4)) {                    // 20480: W^T, vectorized writes
        int n  = i >> 5;                        // output row (0..639)
        int k4 = (i & 31) * 4;                  // k base
        __half2 p0 = __floats2half2_rn(W[(size_t)k4 * HC + n],
                                       W[(size_t)(k4 + 1) * HC + n]);
        __half2 p1 = __floats2half2_rn(W[(size_t)(k4 + 2) * HC + n],
                                       W[(size_t)(k4 + 3) * HC + n]);
        uint2 pk; pk.x = *(unsigned*)&p0; pk.y = *(unsigned*)&p1;
        ((uint2*)g_wt)[i] = pk;
    }
    if (i < Nn * (NPAD / 4))                    // 40000: denom zero
        ((float4*)g_denom)[i] = make_float4(0.f, 0.f, 0.f, 0.f);
}

// ---------------- fp16 TC GEMM, un-chunked K + fused logits -------------------
#define TBM   64
#define AWPAD 68
#define BWPAD 68
#define CH2S  69
#define AS_WORDS (TBM * AWPAD)
#define BS_WORDS (Cn  * BWPAD)
#define SMEM_DYN ((AS_WORDS + BS_WORDS) * 4)   // 52224 B

__device__ __forceinline__ void cp16(unsigned dst, const void* src) {
    asm volatile("cp.async.cg.shared.global [%0], [%1], 16;"
                 :: "r"(dst), "l"(src));
}

__device__ __forceinline__ void mma_f16(float d[4], const unsigned a[4],
                                        const unsigned b[2]) {
    asm volatile(
        "mma.sync.aligned.m16n8k16.row.col.f32.f16.f16.f32 "
        "{%0,%1,%2,%3}, {%4,%5,%6,%7}, {%8,%9}, {%0,%1,%2,%3};"
        : "+f"(d[0]), "+f"(d[1]), "+f"(d[2]), "+f"(d[3])
        : "r"(a[0]), "r"(a[1]), "r"(a[2]), "r"(a[3]), "r"(b[0]), "r"(b[1]));
}

__global__ __launch_bounds__(256, 3)
void gemm_tc_kernel(const float* __restrict__ att_src,
                    const float* __restrict__ att_dst,
                    int M) {
    extern __shared__ __align__(16) char smem_raw[];
    unsigned* As = (unsigned*)smem_raw;
    unsigned* Bs = (unsigned*)smem_raw + AS_WORDS;
    unsigned* Cs = (unsigned*)smem_raw;            // epilogue alias

    const int tid    = threadIdx.x;
    const int head   = blockIdx.x;
    const int rowBlk = blockIdx.y * TBM;
    const int lane   = tid & 31;
    const int wid    = tid >> 5;
    const int warpM  = wid & 1;
    const int warpN  = wid >> 1;
    const int gid    = lane >> 2;
    const int tig    = lane & 3;

    const unsigned sbase = (unsigned)__cvta_generic_to_shared(smem_raw);

    #pragma unroll
    for (int j = 0; j < 4; j++) {
        int idx = tid + j * 256;
        int r = idx >> 4, c = idx & 15;
        int gR = rowBlk + r; if (gR >= M) gR = 0;
        cp16(sbase + (r * AWPAD + c * 4) * 4, g_fh + (size_t)gR * Cn + c * 8);
    }
    #pragma unroll
    for (int j = 0; j < 8; j++) {
        int idx = tid + j * 256;
        int r = idx >> 4, c = idx & 15;
        cp16(sbase + (AS_WORDS + r * BWPAD + c * 4) * 4,
             g_wt + (size_t)(head * Cn + r) * Cn + c * 8);
    }
    asm volatile("cp.async.commit_group;");
    asm volatile("cp.async.wait_group 0;");
    __syncthreads();

    float acc[2][4][4];
    #pragma unroll
    for (int m = 0; m < 2; m++)
        #pragma unroll
        for (int n = 0; n < 4; n++)
            #pragma unroll
            for (int r = 0; r < 4; r++) acc[m][n][r] = 0.0f;

    #pragma unroll
    for (int ks = 0; ks < 8; ks++) {
        const int kw = ks * 8 + tig;
        unsigned a[2][4], b[4][2];
        #pragma unroll
        for (int m = 0; m < 2; m++) {
            int r0 = warpM * 32 + m * 16 + gid;
            a[m][0] = As[r0 * AWPAD + kw];
            a[m][1] = As[(r0 + 8) * AWPAD + kw];
            a[m][2] = As[r0 * AWPAD + kw + 4];
            a[m][3] = As[(r0 + 8) * AWPAD + kw + 4];
        }
        #pragma unroll
        for (int n = 0; n < 4; n++) {
            int cb = warpN * 32 + n * 8 + gid;
            b[n][0] = Bs[cb * BWPAD + kw];
            b[n][1] = Bs[cb * BWPAD + kw + 4];
        }
        #pragma unroll
        for (int m = 0; m < 2; m++)
            #pragma unroll
            for (int n = 0; n < 4; n++)
                mma_f16(acc[m][n], a[m], b[n]);
    }
    __syncthreads();

    #pragma unroll
    for (int m = 0; m < 2; m++) {
        int r0 = warpM * 32 + m * 16 + gid;
        #pragma unroll
        for (int n = 0; n < 4; n++) {
            int ch = warpN * 16 + n * 4 + tig;
            __half2 h01 = __floats2half2_rn(acc[m][n][0], acc[m][n][1]);
            __half2 h23 = __floats2half2_rn(acc[m][n][2], acc[m][n][3]);
            Cs[r0 * CH2S + ch]       = *(unsigned*)&h01;
            Cs[(r0 + 8) * CH2S + ch] = *(unsigned*)&h23;
        }
    }
    __syncthreads();

    // fused attention logits: 4 lanes per row, shfl-reduce width 4
    {
        int row  = tid >> 2;
        int part = tid & 3;
        int gRow = rowBlk + row;
        const float* asv = att_src + head * Cn;
        const float* adv = att_dst + head * Cn;
        float ps = 0.f, pd = 0.f;
        #pragma unroll
        for (int i = 0; i < 16; i++) {
            int ch = part * 16 + i;
            unsigned u = Cs[row * CH2S + ch];
            float2 f = __half22float2(*(__half2*)&u);
            ps = fmaf(f.x, __ldg(asv + 2 * ch), ps);
            ps = fmaf(f.y, __ldg(asv + 2 * ch + 1), ps);
            pd = fmaf(f.x, __ldg(adv + 2 * ch), pd);
            pd = fmaf(f.y, __ldg(adv + 2 * ch + 1), pd);
        }
        ps += __shfl_xor_sync(0xffffffffu, ps, 1, 4);
        ps += __shfl_xor_sync(0xffffffffu, ps, 2, 4);
        pd += __shfl_xor_sync(0xffffffffu, pd, 1, 4);
        pd += __shfl_xor_sync(0xffffffffu, pd, 2, 4);
        if (part == 0 && gRow < M) {
            g_asrc[gRow * NPAD + head] = ps;
            g_adst[gRow * NPAD + head] = pd;
        }
    }

    // coalesced fp16 store to g_h
    unsigned* gh = (unsigned*)g_h;
    #pragma unroll
    for (int i = 0; i < 16; i++) {
        int idx  = i * 256 + tid;
        int row  = idx >> 6;
        int ch   = idx & 63;
        int gRow = rowBlk + row;
        if (gRow < M)
            gh[(size_t)gRow * (HC / 2) + head * 64 + ch] = Cs[row * CH2S + ch];
    }
}

// ---------------- kernel 2: softmax denominators, vectorized ------------------
__global__ void denom_kernel(const int* __restrict__ ei, int E, int Etot) {
    int e = blockIdx.x * blockDim.x + threadIdx.x;
    if (e >= Etot) return;
    int src, dst;
    if (e < E) { src = ei[e]; dst = ei[E + e]; }
    else       { src = e - E; dst = src; }

    float4 s4 = __ldg((const float4*)(g_asrc + src * NPAD));
    float  s5 = __ldg(g_asrc + src * NPAD + 4);
    float4 d4 = __ldg((const float4*)(g_adst + dst * NPAD));
    float  d5 = __ldg(g_adst + dst * NPAD + 4);

    float v0 = s4.x + d4.x, v1 = s4.y + d4.y, v2 = s4.z + d4.z,
          v3 = s4.w + d4.w, v4 = s5 + d5;
    v0 = v0 > 0.f ? v0 : NEG_SLOPE * v0;
    v1 = v1 > 0.f ? v1 : NEG_SLOPE * v1;
    v2 = v2 > 0.f ? v2 : NEG_SLOPE * v2;
    v3 = v3 > 0.f ? v3 : NEG_SLOPE * v3;
    v4 = v4 > 0.f ? v4 : NEG_SLOPE * v4;
    float t0 = __expf(v0), t1 = __expf(v1), t2 = __expf(v2),
          t3 = __expf(v3), t4 = __expf(v4);

    float* dp = g_denom + dst * NPAD;
    asm volatile("red.global.add.v4.f32 [%0], {%1, %2, %3, %4};"
                 :: "l"(dp), "f"(t0), "f"(t1), "f"(t2), "f"(t3) : "memory");
    asm volatile("red.global.add.f32 [%0], %1;"
                 :: "l"(dp + 4), "f"(t4) : "memory");
}

// ---------------- helper: accumulate 4 fp16 channels of one head -------------
__device__ __forceinline__ void acc_head(float4& acc4, uint2 u, float wgt) {
    float2 lo = __half22float2(*(const __half2*)&u.x);
    float2 hi = __half22float2(*(const __half2*)&u.y);
    acc4.x = fmaf(wgt, lo.x, acc4.x);
    acc4.y = fmaf(wgt, lo.y, acc4.y);
    acc4.z = fmaf(wgt, hi.x, acc4.z);
    acc4.w = fmaf(wgt, hi.y, acc4.w);
}

__device__ __forceinline__ float edge_w(int s, int d, int h) {
    float v = g_asrc[s * NPAD + h] + g_adst[d * NPAD + h];
    v = v > 0.f ? v : NEG_SLOPE * v;
    return __expf(v) / (g_denom[d * NPAD + h] + EPSV) * (1.0f / Hh);
}

// ---------------- kernel 3: scatter, 2 independent edges per warp ------------
__global__ __launch_bounds__(256)
void scatter_kernel(const int* __restrict__ ei,
                    float* __restrict__ out, int E, int Etot) {
    const int warp = threadIdx.x >> 5;
    const int lane = threadIdx.x & 31;
    const int e0 = (blockIdx.x * 8 + warp) * 2;
    const int e1 = e0 + 1;
    const bool v0 = (e0 < Etot);
    const bool v1 = (e1 < Etot);
    const int ec0 = v0 ? e0 : 0;
    const int ec1 = v1 ? e1 : 0;

    int s0, d0, s1, d1;
    if (ec0 < E) { s0 = ei[ec0]; d0 = ei[E + ec0]; } else { s0 = ec0 - E; d0 = s0; }
    if (ec1 < E) { s1 = ei[ec1]; d1 = ei[E + ec1]; } else { s1 = ec1 - E; d1 = s1; }

    // lanes 0..4 -> edge0 weights; lanes 8..12 -> edge1 weights
    float wv = 0.f;
    if (lane < Hh)                     wv = edge_w(s0, d0, lane);
    else if (lane >= 8 && lane < 8 + Hh) wv = edge_w(s1, d1, lane - 8);

    float w0 = __shfl_sync(0xffffffffu, wv, 0);
    float w1 = __shfl_sync(0xffffffffu, wv, 1);
    float w2 = __shfl_sync(0xffffffffu, wv, 2);
    float w3 = __shfl_sync(0xffffffffu, wv, 3);
    float w4 = __shfl_sync(0xffffffffu, wv, 4);
    float x0 = __shfl_sync(0xffffffffu, wv, 8);
    float x1 = __shfl_sync(0xffffffffu, wv, 9);
    float x2 = __shfl_sync(0xffffffffu, wv, 10);
    float x3 = __shfl_sync(0xffffffffu, wv, 11);
    float x4 = __shfl_sync(0xffffffffu, wv, 12);

    // 10 independent h loads (2 edges x 5 heads)
    const uint2* hp0 = (const uint2*)(g_h + (size_t)s0 * HC) + lane;
    const uint2* hp1 = (const uint2*)(g_h + (size_t)s1 * HC) + lane;
    uint2 a0 = hp0[0 * 32], a1 = hp0[1 * 32], a2 = hp0[2 * 32],
          a3 = hp0[3 * 32], a4 = hp0[4 * 32];
    uint2 b0 = hp1[0 * 32], b1 = hp1[1 * 32], b2 = hp1[2 * 32],
          b3 = hp1[3 * 32], b4 = hp1[4 * 32];

    float4 accA = make_float4(0.f, 0.f, 0.f, 0.f);
    float4 accB = make_float4(0.f, 0.f, 0.f, 0.f);
    acc_head(accA, a0, w0); acc_head(accB, b0, x0);
    acc_head(accA, a1, w1); acc_head(accB, b1, x1);
    acc_head(accA, a2, w2); acc_head(accB, b2, x2);
    acc_head(accA, a3, w3); acc_head(accB, b3, x3);
    acc_head(accA, a4, w4); acc_head(accB, b4, x4);

    if (v0) {
        float* op = out + (size_t)d0 * Cn + lane * 4;
        asm volatile("red.global.add.v4.f32 [%0], {%1, %2, %3, %4};"
                     :: "l"(op), "f"(accA.x), "f"(accA.y), "f"(accA.z), "f"(accA.w)
                     : "memory");
    }
    if (v1) {
        float* op = out + (size_t)d1 * Cn + lane * 4;
        asm volatile("red.global.add.v4.f32 [%0], {%1, %2, %3, %4};"
                     :: "l"(op), "f"(accB.x), "f"(accB.y), "f"(accB.z), "f"(accB.w)
                     : "memory");
    }
}

// ---------------- launch -------------------------------------------------------
extern "C" void kernel_launch(void* const* d_in, const int* in_sizes, int n_in,
                              void* d_out, int out_size) {
    const float* features = (const float*)d_in[0];
    const float* W        = (const float*)d_in[1];
    const float* att_src  = (const float*)d_in[2];
    const float* att_dst  = (const float*)d_in[3];
    const float* bias     = (const float*)d_in[4];
    const int*   ei       = (const int*)d_in[5];
    float*       out      = (float*)d_out;

    const int Nn   = in_sizes[0] / Cn;   // 20000
    const int E    = in_sizes[5] / 2;    // 320000
    const int Etot = E + Nn;             // 340000

    // 0) prep: out = features + bias, fp16 converts, denom zero (vectorized)
    {
        int work = Nn * (Cn / 4);        // 640000, covers all three ranges
        prep_kernel<<<(work + 255) / 256, 256>>>((const float4*)features, W,
                                                 (const float4*)bias,
                                                 (float4*)out, Nn);
    }

    // 1) GEMM (fp16 TC, un-chunked K) + fused logits
    {
        cudaFuncSetAttribute(gemm_tc_kernel,
                             cudaFuncAttributeMaxDynamicSharedMemorySize, SMEM_DYN);
        dim3 grid(Hh, (Nn + TBM - 1) / TBM);   // (5, 313)
        gemm_tc_kernel<<<grid, 256, SMEM_DYN>>>(att_src, att_dst, Nn);
    }

    // 2) softmax denominators (vectorized loads + v4 atomics)
    denom_kernel<<<(Etot + 255) / 256, 256>>>(ei, E, Etot);

    // 3) scatter: 2 edges per warp, 16 edges per block
    scatter_kernel<<<(Etot + 15) / 16, 256>>>(ei, out, E, Etot);
}

// round 16
// speedup vs baseline: 1.2708x; 1.0029x over previous
#include <cuda_runtime.h>
#include <cuda_fp16.h>
#include <math.h>

// Problem constants (fixed by the dataset)
#define Cn   128
#define Hh   5
#define NPAD 8            // per-node stride for asrc/denom: 32 B, v4-aligned
#define DDS  16           // g_dd per-node stride: [0..4]=adst, [8..12]=rdenom (64 B line)
#define HC   (Hh*Cn)      // 640
#define MAXN 20000
#define MAXE 320000
#define MAXET (MAXE + MAXN)
#define EPSV 1e-16f
#define NEG_SLOPE 0.2f

// ---------------- scratch (static device globals) -----------------------------
__device__ __align__(16) __half g_h[(size_t)MAXN * HC];   // [N,H,C] fp16 (25.6 MB)
__device__ __align__(16) __half g_fh[(size_t)MAXN * Cn];  // features fp16 (5.1 MB)
__device__ __align__(16) __half g_wt[HC * Cn];            // W^T fp16 [n][k]
__device__ __align__(16) float g_asrc[MAXN * NPAD];
__device__ __align__(16) float g_denom[MAXN * NPAD];
__device__ __align__(64) float g_dd[MAXN * DDS];          // adst + rdenom packed

// ---------------- kernel 0: prep (vectorized) ---------------------------------
__global__ void prep_kernel(const float4* __restrict__ features4,
                            const float*  __restrict__ W,
                            const float4* __restrict__ bias4,
                            float4* __restrict__ out4, int Nn) {
    int i = blockIdx.x * blockDim.x + threadIdx.x;
    int NC4 = Nn * (Cn / 4);                    // 640000
    if (i < NC4) {
        float4 f = features4[i];
        float4 b = bias4[i & 31];
        out4[i] = make_float4(f.x + b.x, f.y + b.y, f.z + b.z, f.w + b.w);
        __half2 h01 = __floats2half2_rn(f.x, f.y);
        __half2 h23 = __floats2half2_rn(f.z, f.w);
        uint2 pk; pk.x = *(unsigned*)&h01; pk.y = *(unsigned*)&h23;
        ((uint2*)g_fh)[i] = pk;
    }
    if (i < HC * (Cn / 4)) {                    // 20480: W^T, vectorized writes
        int n  = i >> 5;
        int k4 = (i & 31) * 4;
        __half2 p0 = __floats2half2_rn(W[(size_t)k4 * HC + n],
                                       W[(size_t)(k4 + 1) * HC + n]);
        __half2 p1 = __floats2half2_rn(W[(size_t)(k4 + 2) * HC + n],
                                       W[(size_t)(k4 + 3) * HC + n]);
        uint2 pk; pk.x = *(unsigned*)&p0; pk.y = *(unsigned*)&p1;
        ((uint2*)g_wt)[i] = pk;
    }
    if (i < Nn * (NPAD / 4))                    // 40000: denom zero
        ((float4*)g_denom)[i] = make_float4(0.f, 0.f, 0.f, 0.f);
}

// ---------------- fp16 TC GEMM, un-chunked K + fused logits -------------------
#define TBM   64
#define AWPAD 68
#define BWPAD 68
#define CH2S  69
#define AS_WORDS (TBM * AWPAD)
#define BS_WORDS (Cn  * BWPAD)
#define SMEM_DYN ((AS_WORDS + BS_WORDS) * 4)   // 52224 B

__device__ __forceinline__ void cp16(unsigned dst, const void* src) {
    asm volatile("cp.async.cg.shared.global [%0], [%1], 16;"
                 :: "r"(dst), "l"(src));
}

__device__ __forceinline__ void mma_f16(float d[4], const unsigned a[4],
                                        const unsigned b[2]) {
    asm volatile(
        "mma.sync.aligned.m16n8k16.row.col.f32.f16.f16.f32 "
        "{%0,%1,%2,%3}, {%4,%5,%6,%7}, {%8,%9}, {%0,%1,%2,%3};"
        : "+f"(d[0]), "+f"(d[1]), "+f"(d[2]), "+f"(d[3])
        : "r"(a[0]), "r"(a[1]), "r"(a[2]), "r"(a[3]), "r"(b[0]), "r"(b[1]));
}

__global__ __launch_bounds__(256, 3)
void gemm_tc_kernel(const float* __restrict__ att_src,
                    const float* __restrict__ att_dst,
                    int M) {
    extern __shared__ __align__(16) char smem_raw[];
    unsigned* As = (unsigned*)smem_raw;
    unsigned* Bs = (unsigned*)smem_raw + AS_WORDS;
    unsigned* Cs = (unsigned*)smem_raw;            // epilogue alias

    const int tid    = threadIdx.x;
    const int head   = blockIdx.x;
    const int rowBlk = blockIdx.y * TBM;
    const int lane   = tid & 31;
    const int wid    = tid >> 5;
    const int warpM  = wid & 1;
    const int warpN  = wid >> 1;
    const int gid    = lane >> 2;
    const int tig    = lane & 3;

    const unsigned sbase = (unsigned)__cvta_generic_to_shared(smem_raw);

    #pragma unroll
    for (int j = 0; j < 4; j++) {
        int idx = tid + j * 256;
        int r = idx >> 4, c = idx & 15;
        int gR = rowBlk + r; if (gR >= M) gR = 0;
        cp16(sbase + (r * AWPAD + c * 4) * 4, g_fh + (size_t)gR * Cn + c * 8);
    }
    #pragma unroll
    for (int j = 0; j < 8; j++) {
        int idx = tid + j * 256;
        int r = idx >> 4, c = idx & 15;
        cp16(sbase + (AS_WORDS + r * BWPAD + c * 4) * 4,
             g_wt + (size_t)(head * Cn + r) * Cn + c * 8);
    }
    asm volatile("cp.async.commit_group;");
    asm volatile("cp.async.wait_group 0;");
    __syncthreads();

    float acc[2][4][4];
    #pragma unroll
    for (int m = 0; m < 2; m++)
        #pragma unroll
        for (int n = 0; n < 4; n++)
            #pragma unroll
            for (int r = 0; r < 4; r++) acc[m][n][r] = 0.0f;

    #pragma unroll
    for (int ks = 0; ks < 8; ks++) {
        const int kw = ks * 8 + tig;
        unsigned a[2][4], b[4][2];
        #pragma unroll
        for (int m = 0; m < 2; m++) {
            int r0 = warpM * 32 + m * 16 + gid;
            a[m][0] = As[r0 * AWPAD + kw];
            a[m][1] = As[(r0 + 8) * AWPAD + kw];
            a[m][2] = As[r0 * AWPAD + kw + 4];
            a[m][3] = As[(r0 + 8) * AWPAD + kw + 4];
        }
        #pragma unroll
        for (int n = 0; n < 4; n++) {
            int cb = warpN * 32 + n * 8 + gid;
            b[n][0] = Bs[cb * BWPAD + kw];
            b[n][1] = Bs[cb * BWPAD + kw + 4];
        }
        #pragma unroll
        for (int m = 0; m < 2; m++)
            #pragma unroll
            for (int n = 0; n < 4; n++)
                mma_f16(acc[m][n], a[m], b[n]);
    }
    __syncthreads();

    #pragma unroll
    for (int m = 0; m < 2; m++) {
        int r0 = warpM * 32 + m * 16 + gid;
        #pragma unroll
        for (int n = 0; n < 4; n++) {
            int ch = warpN * 16 + n * 4 + tig;
            __half2 h01 = __floats2half2_rn(acc[m][n][0], acc[m][n][1]);
            __half2 h23 = __floats2half2_rn(acc[m][n][2], acc[m][n][3]);
            Cs[r0 * CH2S + ch]       = *(unsigned*)&h01;
            Cs[(r0 + 8) * CH2S + ch] = *(unsigned*)&h23;
        }
    }
    __syncthreads();

    // fused attention logits: 4 lanes per row, shfl-reduce width 4
    {
        int row  = tid >> 2;
        int part = tid & 3;
        int gRow = rowBlk + row;
        const float* asv = att_src + head * Cn;
        const float* adv = att_dst + head * Cn;
        float ps = 0.f, pd = 0.f;
        #pragma unroll
        for (int i = 0; i < 16; i++) {
            int ch = part * 16 + i;
            unsigned u = Cs[row * CH2S + ch];
            float2 f = __half22float2(*(__half2*)&u);
            ps = fmaf(f.x, __ldg(asv + 2 * ch), ps);
            ps = fmaf(f.y, __ldg(asv + 2 * ch + 1), ps);
            pd = fmaf(f.x, __ldg(adv + 2 * ch), pd);
            pd = fmaf(f.y, __ldg(adv + 2 * ch + 1), pd);
        }
        ps += __shfl_xor_sync(0xffffffffu, ps, 1, 4);
        ps += __shfl_xor_sync(0xffffffffu, ps, 2, 4);
        pd += __shfl_xor_sync(0xffffffffu, pd, 1, 4);
        pd += __shfl_xor_sync(0xffffffffu, pd, 2, 4);
        if (part == 0 && gRow < M) {
            g_asrc[gRow * NPAD + head] = ps;
            g_dd[gRow * DDS + head]    = pd;     // adst into packed struct
        }
    }

    // coalesced fp16 store to g_h
    unsigned* gh = (unsigned*)g_h;
    #pragma unroll
    for (int i = 0; i < 16; i++) {
        int idx  = i * 256 + tid;
        int row  = idx >> 6;
        int ch   = idx & 63;
        int gRow = rowBlk + row;
        if (gRow < M)
            gh[(size_t)gRow * (HC / 2) + head * 64 + ch] = Cs[row * CH2S + ch];
    }
}

// ---------------- kernel 2: softmax denominators, vectorized ------------------
__global__ void denom_kernel(const int* __restrict__ ei, int E, int Etot) {
    int e = blockIdx.x * blockDim.x + threadIdx.x;
    if (e >= Etot) return;
    int src, dst;
    if (e < E) { src = ei[e]; dst = ei[E + e]; }
    else       { src = e - E; dst = src; }

    float4 s4 = __ldg((const float4*)(g_asrc + src * NPAD));
    float  s5 = __ldg(g_asrc + src * NPAD + 4);
    float4 d4 = __ldg((const float4*)(g_dd + dst * DDS));
    float  d5 = __ldg(g_dd + dst * DDS + 4);

    float v0 = s4.x + d4.x, v1 = s4.y + d4.y, v2 = s4.z + d4.z,
          v3 = s4.w + d4.w, v4 = s5 + d5;
    v0 = v0 > 0.f ? v0 : NEG_SLOPE * v0;
    v1 = v1 > 0.f ? v1 : NEG_SLOPE * v1;
    v2 = v2 > 0.f ? v2 : NEG_SLOPE * v2;
    v3 = v3 > 0.f ? v3 : NEG_SLOPE * v3;
    v4 = v4 > 0.f ? v4 : NEG_SLOPE * v4;
    float t0 = __expf(v0), t1 = __expf(v1), t2 = __expf(v2),
          t3 = __expf(v3), t4 = __expf(v4);

    float* dp = g_denom + dst * NPAD;
    asm volatile("red.global.add.v4.f32 [%0], {%1, %2, %3, %4};"
                 :: "l"(dp), "f"(t0), "f"(t1), "f"(t2), "f"(t3) : "memory");
    asm volatile("red.global.add.f32 [%0], %1;"
                 :: "l"(dp + 4), "f"(t4) : "memory");
}

// ---------------- kernel 2.5: rdenom = (1/H)/(denom+eps), packed into g_dd ----
__global__ void rdenom_kernel(int n) {
    int i = blockIdx.x * blockDim.x + threadIdx.x;
    if (i >= n) return;
    int node = i / Hh, h = i - node * Hh;
    g_dd[node * DDS + 8 + h] = (1.0f / Hh) / (g_denom[node * NPAD + h] + EPSV);
}

// ---------------- helper: accumulate 4 fp16 channels of one head -------------
__device__ __forceinline__ void acc_head(float4& acc4, uint2 u, float wgt) {
    float2 lo = __half22float2(*(const __half2*)&u.x);
    float2 hi = __half22float2(*(const __half2*)&u.y);
    acc4.x = fmaf(wgt, lo.x, acc4.x);
    acc4.y = fmaf(wgt, lo.y, acc4.y);
    acc4.z = fmaf(wgt, hi.x, acc4.z);
    acc4.w = fmaf(wgt, hi.y, acc4.w);
}

// weight = exp(leaky(asrc+adst)) * rdenom (adst & rdenom share one cache line)
__device__ __forceinline__ float edge_w(int s, int d, int h) {
    float v = g_asrc[s * NPAD + h] + g_dd[d * DDS + h];
    v = v > 0.f ? v : NEG_SLOPE * v;
    return __expf(v) * g_dd[d * DDS + 8 + h];
}

// ---------------- kernel 3: scatter, 2 independent edges per warp ------------
__global__ __launch_bounds__(256)
void scatter_kernel(const int* __restrict__ ei,
                    float* __restrict__ out, int E, int Etot) {
    const int warp = threadIdx.x >> 5;
    const int lane = threadIdx.x & 31;
    const int e0 = (blockIdx.x * 8 + warp) * 2;
    const int e1 = e0 + 1;
    const bool v0 = (e0 < Etot);
    const bool v1 = (e1 < Etot);
    const int ec0 = v0 ? e0 : 0;
    const int ec1 = v1 ? e1 : 0;

    int s0, d0, s1, d1;
    if (ec0 < E) { s0 = ei[ec0]; d0 = ei[E + ec0]; } else { s0 = ec0 - E; d0 = s0; }
    if (ec1 < E) { s1 = ei[ec1]; d1 = ei[E + ec1]; } else { s1 = ec1 - E; d1 = s1; }

    // lanes 0..4 -> edge0 weights; lanes 8..12 -> edge1 weights
    float wv = 0.f;
    if (lane < Hh)                       wv = edge_w(s0, d0, lane);
    else if (lane >= 8 && lane < 8 + Hh) wv = edge_w(s1, d1, lane - 8);

    float w0 = __shfl_sync(0xffffffffu, wv, 0);
    float w1 = __shfl_sync(0xffffffffu, wv, 1);
    float w2 = __shfl_sync(0xffffffffu, wv, 2);
    float w3 = __shfl_sync(0xffffffffu, wv, 3);
    float w4 = __shfl_sync(0xffffffffu, wv, 4);
    float x0 = __shfl_sync(0xffffffffu, wv, 8);
    float x1 = __shfl_sync(0xffffffffu, wv, 9);
    float x2 = __shfl_sync(0xffffffffu, wv, 10);
    float x3 = __shfl_sync(0xffffffffu, wv, 11);
    float x4 = __shfl_sync(0xffffffffu, wv, 12);

    const uint2* hp0 = (const uint2*)(g_h + (size_t)s0 * HC) + lane;
    const uint2* hp1 = (const uint2*)(g_h + (size_t)s1 * HC) + lane;
    uint2 a0 = hp0[0 * 32], a1 = hp0[1 * 32], a2 = hp0[2 * 32],
          a3 = hp0[3 * 32], a4 = hp0[4 * 32];
    uint2 b0 = hp1[0 * 32], b1 = hp1[1 * 32], b2 = hp1[2 * 32],
          b3 = hp1[3 * 32], b4 = hp1[4 * 32];

    float4 accA = make_float4(0.f, 0.f, 0.f, 0.f);
    float4 accB = make_float4(0.f, 0.f, 0.f, 0.f);
    acc_head(accA, a0, w0); acc_head(accB, b0, x0);
    acc_head(accA, a1, w1); acc_head(accB, b1, x1);
    acc_head(accA, a2, w2); acc_head(accB, b2, x2);
    acc_head(accA, a3, w3); acc_head(accB, b3, x3);
    acc_head(accA, a4, w4); acc_head(accB, b4, x4);

    if (v0) {
        float* op = out + (size_t)d0 * Cn + lane * 4;
        asm volatile("red.global.add.v4.f32 [%0], {%1, %2, %3, %4};"
                     :: "l"(op), "f"(accA.x), "f"(accA.y), "f"(accA.z), "f"(accA.w)
                     : "memory");
    }
    if (v1) {
        float* op = out + (size_t)d1 * Cn + lane * 4;
        asm volatile("red.global.add.v4.f32 [%0], {%1, %2, %3, %4};"
                     :: "l"(op), "f"(accB.x), "f"(accB.y), "f"(accB.z), "f"(accB.w)
                     : "memory");
    }
}

// ---------------- launch -------------------------------------------------------
extern "C" void kernel_launch(void* const* d_in, const int* in_sizes, int n_in,
                              void* d_out, int out_size) {
    const float* features = (const float*)d_in[0];
    const float* W        = (const float*)d_in[1];
    const float* att_src  = (const float*)d_in[2];
    const float* att_dst  = (const float*)d_in[3];
    const float* bias     = (const float*)d_in[4];
    const int*   ei       = (const int*)d_in[5];
    float*       out      = (float*)d_out;

    const int Nn   = in_sizes[0] / Cn;   // 20000
    const int E    = in_sizes[5] / 2;    // 320000
    const int Etot = E + Nn;             // 340000

    // 0) prep: out = features + bias, fp16 converts, denom zero (vectorized)
    {
        int work = Nn * (Cn / 4);        // 640000, covers all ranges
        prep_kernel<<<(work + 255) / 256, 256>>>((const float4*)features, W,
                                                 (const float4*)bias,
                                                 (float4*)out, Nn);
    }

    // 1) GEMM (fp16 TC, un-chunked K) + fused logits (adst -> g_dd)
    {
        cudaFuncSetAttribute(gemm_tc_kernel,
                             cudaFuncAttributeMaxDynamicSharedMemorySize, SMEM_DYN);
        dim3 grid(Hh, (Nn + TBM - 1) / TBM);   // (5, 313)
        gemm_tc_kernel<<<grid, 256, SMEM_DYN>>>(att_src, att_dst, Nn);
    }

    // 2) softmax denominators (vectorized loads + v4 atomics)
    denom_kernel<<<(Etot + 255) / 256, 256>>>(ei, E, Etot);

    // 2.5) reciprocal denominators, packed next to adst
    rdenom_kernel<<<(Nn * Hh + 255) / 256, 256>>>(Nn * Hh);

    // 3) scatter: 2 edges per warp, no divisions
    scatter_kernel<<<(Etot + 15) / 16, 256>>>(ei, out, E, Etot);
}

// round 17
// speedup vs baseline: 1.3333x; 1.0492x over previous
#include <cuda_runtime.h>
#include <cuda_fp16.h>
#include <math.h>

// Problem constants (fixed by the dataset)
#define Cn   128
#define Hh   5
#define NPAD 8            // per-node stride for asrc/denom: 32 B, v4-aligned
#define DDS  16           // g_dd per-node stride: [0..4]=adst, [8..12]=rdenom (64 B line)
#define HC   (Hh*Cn)      // 640
#define MAXN 20000
#define MAXE 320000
#define MAXET (MAXE + MAXN)
#define EPSV 1e-16f
#define NEG_SLOPE 0.2f

// ---------------- scratch (static device globals) -----------------------------
__device__ __align__(16) __half g_h[(size_t)MAXN * HC];   // [N,H,C] fp16 (25.6 MB)
__device__ __align__(16) __half g_fh[(size_t)MAXN * Cn];  // features fp16 (5.1 MB)
__device__ __align__(16) __half g_wt[HC * Cn];            // W^T fp16 [n][k]
__device__ __align__(16) float g_asrc[MAXN * NPAD];
__device__ __align__(16) float g_denom[MAXN * NPAD];
__device__ __align__(64) float g_dd[MAXN * DDS];          // adst + rdenom packed

// ---------------- kernel 0: prep (vectorized) ---------------------------------
__global__ void prep_kernel(const float4* __restrict__ features4,
                            const float*  __restrict__ W,
                            const float4* __restrict__ bias4,
                            float4* __restrict__ out4, int Nn) {
    int i = blockIdx.x * blockDim.x + threadIdx.x;
    int NC4 = Nn * (Cn / 4);                    // 640000
    if (i < NC4) {
        float4 f = features4[i];
        float4 b = bias4[i & 31];
        out4[i] = make_float4(f.x + b.x, f.y + b.y, f.z + b.z, f.w + b.w);
        __half2 h01 = __floats2half2_rn(f.x, f.y);
        __half2 h23 = __floats2half2_rn(f.z, f.w);
        uint2 pk; pk.x = *(unsigned*)&h01; pk.y = *(unsigned*)&h23;
        ((uint2*)g_fh)[i] = pk;
    }
    if (i < HC * (Cn / 4)) {                    // 20480: W^T, vectorized writes
        int n  = i >> 5;
        int k4 = (i & 31) * 4;
        __half2 p0 = __floats2half2_rn(W[(size_t)k4 * HC + n],
                                       W[(size_t)(k4 + 1) * HC + n]);
        __half2 p1 = __floats2half2_rn(W[(size_t)(k4 + 2) * HC + n],
                                       W[(size_t)(k4 + 3) * HC + n]);
        uint2 pk; pk.x = *(unsigned*)&p0; pk.y = *(unsigned*)&p1;
        ((uint2*)g_wt)[i] = pk;
    }
    if (i < Nn * (NPAD / 4))                    // 40000: denom zero
        ((float4*)g_denom)[i] = make_float4(0.f, 0.f, 0.f, 0.f);
}

// ---------------- fp16 TC GEMM, un-chunked K + fused logits -------------------
#define TBM   64
#define AWPAD 68
#define BWPAD 68
#define CH2S  69
#define AS_WORDS (TBM * AWPAD)
#define BS_WORDS (Cn  * BWPAD)
#define SMEM_DYN ((AS_WORDS + BS_WORDS) * 4)   // 52224 B

__device__ __forceinline__ void cp16(unsigned dst, const void* src) {
    asm volatile("cp.async.cg.shared.global [%0], [%1], 16;"
                 :: "r"(dst), "l"(src));
}

__device__ __forceinline__ void mma_f16(float d[4], const unsigned a[4],
                                        const unsigned b[2]) {
    asm volatile(
        "mma.sync.aligned.m16n8k16.row.col.f32.f16.f16.f32 "
        "{%0,%1,%2,%3}, {%4,%5,%6,%7}, {%8,%9}, {%0,%1,%2,%3};"
        : "+f"(d[0]), "+f"(d[1]), "+f"(d[2]), "+f"(d[3])
        : "r"(a[0]), "r"(a[1]), "r"(a[2]), "r"(a[3]), "r"(b[0]), "r"(b[1]));
}

__global__ __launch_bounds__(256, 3)
void gemm_tc_kernel(const float* __restrict__ att_src,
                    const float* __restrict__ att_dst,
                    int M) {
    extern __shared__ __align__(16) char smem_raw[];
    unsigned* As = (unsigned*)smem_raw;
    unsigned* Bs = (unsigned*)smem_raw + AS_WORDS;
    unsigned* Cs = (unsigned*)smem_raw;            // epilogue alias

    const int tid    = threadIdx.x;
    const int head   = blockIdx.x;
    const int rowBlk = blockIdx.y * TBM;
    const int lane   = tid & 31;
    const int wid    = tid >> 5;
    const int warpM  = wid & 1;
    const int warpN  = wid >> 1;
    const int gid    = lane >> 2;
    const int tig    = lane & 3;

    const unsigned sbase = (unsigned)__cvta_generic_to_shared(smem_raw);

    #pragma unroll
    for (int j = 0; j < 4; j++) {
        int idx = tid + j * 256;
        int r = idx >> 4, c = idx & 15;
        int gR = rowBlk + r; if (gR >= M) gR = 0;
        cp16(sbase + (r * AWPAD + c * 4) * 4, g_fh + (size_t)gR * Cn + c * 8);
    }
    #pragma unroll
    for (int j = 0; j < 8; j++) {
        int idx = tid + j * 256;
        int r = idx >> 4, c = idx & 15;
        cp16(sbase + (AS_WORDS + r * BWPAD + c * 4) * 4,
             g_wt + (size_t)(head * Cn + r) * Cn + c * 8);
    }
    asm volatile("cp.async.commit_group;");
    asm volatile("cp.async.wait_group 0;");
    __syncthreads();

    float acc[2][4][4];
    #pragma unroll
    for (int m = 0; m < 2; m++)
        #pragma unroll
        for (int n = 0; n < 4; n++)
            #pragma unroll
            for (int r = 0; r < 4; r++) acc[m][n][r] = 0.0f;

    #pragma unroll
    for (int ks = 0; ks < 8; ks++) {
        const int kw = ks * 8 + tig;
        unsigned a[2][4], b[4][2];
        #pragma unroll
        for (int m = 0; m < 2; m++) {
            int r0 = warpM * 32 + m * 16 + gid;
            a[m][0] = As[r0 * AWPAD + kw];
            a[m][1] = As[(r0 + 8) * AWPAD + kw];
            a[m][2] = As[r0 * AWPAD + kw + 4];
            a[m][3] = As[(r0 + 8) * AWPAD + kw + 4];
        }
        #pragma unroll
        for (int n = 0; n < 4; n++) {
            int cb = warpN * 32 + n * 8 + gid;
            b[n][0] = Bs[cb * BWPAD + kw];
            b[n][1] = Bs[cb * BWPAD + kw + 4];
        }
        #pragma unroll
        for (int m = 0; m < 2; m++)
            #pragma unroll
            for (int n = 0; n < 4; n++)
                mma_f16(acc[m][n], a[m], b[n]);
    }
    __syncthreads();

    #pragma unroll
    for (int m = 0; m < 2; m++) {
        int r0 = warpM * 32 + m * 16 + gid;
        #pragma unroll
        for (int n = 0; n < 4; n++) {
            int ch = warpN * 16 + n * 4 + tig;
            __half2 h01 = __floats2half2_rn(acc[m][n][0], acc[m][n][1]);
            __half2 h23 = __floats2half2_rn(acc[m][n][2], acc[m][n][3]);
            Cs[r0 * CH2S + ch]       = *(unsigned*)&h01;
            Cs[(r0 + 8) * CH2S + ch] = *(unsigned*)&h23;
        }
    }
    __syncthreads();

    // fused attention logits: 4 lanes per row, shfl-reduce width 4
    {
        int row  = tid >> 2;
        int part = tid & 3;
        int gRow = rowBlk + row;
        const float* asv = att_src + head * Cn;
        const float* adv = att_dst + head * Cn;
        float ps = 0.f, pd = 0.f;
        #pragma unroll
        for (int i = 0; i < 16; i++) {
            int ch = part * 16 + i;
            unsigned u = Cs[row * CH2S + ch];
            float2 f = __half22float2(*(__half2*)&u);
            ps = fmaf(f.x, __ldg(asv + 2 * ch), ps);
            ps = fmaf(f.y, __ldg(asv + 2 * ch + 1), ps);
            pd = fmaf(f.x, __ldg(adv + 2 * ch), pd);
            pd = fmaf(f.y, __ldg(adv + 2 * ch + 1), pd);
        }
        ps += __shfl_xor_sync(0xffffffffu, ps, 1, 4);
        ps += __shfl_xor_sync(0xffffffffu, ps, 2, 4);
        pd += __shfl_xor_sync(0xffffffffu, pd, 1, 4);
        pd += __shfl_xor_sync(0xffffffffu, pd, 2, 4);
        if (part == 0 && gRow < M) {
            g_asrc[gRow * NPAD + head] = ps;
            g_dd[gRow * DDS + head]    = pd;
        }
    }

    // coalesced fp16 store to g_h
    unsigned* gh = (unsigned*)g_h;
    #pragma unroll
    for (int i = 0; i < 16; i++) {
        int idx  = i * 256 + tid;
        int row  = idx >> 6;
        int ch   = idx & 63;
        int gRow = rowBlk + row;
        if (gRow < M)
            gh[(size_t)gRow * (HC / 2) + head * 64 + ch] = Cs[row * CH2S + ch];
    }
}

// ---------------- kernel 2: softmax denominators, vectorized ------------------
__global__ void denom_kernel(const int* __restrict__ ei, int E, int Etot) {
    int e = blockIdx.x * blockDim.x + threadIdx.x;
    if (e >= Etot) return;
    int src, dst;
    if (e < E) { src = ei[e]; dst = ei[E + e]; }
    else       { src = e - E; dst = src; }

    float4 s4 = __ldg((const float4*)(g_asrc + src * NPAD));
    float  s5 = __ldg(g_asrc + src * NPAD + 4);
    float4 d4 = __ldg((const float4*)(g_dd + dst * DDS));
    float  d5 = __ldg(g_dd + dst * DDS + 4);

    float v0 = s4.x + d4.x, v1 = s4.y + d4.y, v2 = s4.z + d4.z,
          v3 = s4.w + d4.w, v4 = s5 + d5;
    v0 = v0 > 0.f ? v0 : NEG_SLOPE * v0;
    v1 = v1 > 0.f ? v1 : NEG_SLOPE * v1;
    v2 = v2 > 0.f ? v2 : NEG_SLOPE * v2;
    v3 = v3 > 0.f ? v3 : NEG_SLOPE * v3;
    v4 = v4 > 0.f ? v4 : NEG_SLOPE * v4;
    float t0 = __expf(v0), t1 = __expf(v1), t2 = __expf(v2),
          t3 = __expf(v3), t4 = __expf(v4);

    float* dp = g_denom + dst * NPAD;
    asm volatile("red.global.add.v4.f32 [%0], {%1, %2, %3, %4};"
                 :: "l"(dp), "f"(t0), "f"(t1), "f"(t2), "f"(t3) : "memory");
    asm volatile("red.global.add.f32 [%0], %1;"
                 :: "l"(dp + 4), "f"(t4) : "memory");
}

// ---------------- kernel 2.5: rdenom = (1/H)/(denom+eps), packed into g_dd ----
__global__ void rdenom_kernel(int n) {
    int i = blockIdx.x * blockDim.x + threadIdx.x;
    if (i >= n) return;
    int node = i / Hh, h = i - node * Hh;
    g_dd[node * DDS + 8 + h] = (1.0f / Hh) / (g_denom[node * NPAD + h] + EPSV);
}

// weight = exp(leaky(asrc+adst)) * rdenom (adst & rdenom share one cache line)
__device__ __forceinline__ float edge_w(int s, int d, int h) {
    float v = g_asrc[s * NPAD + h] + g_dd[d * DDS + h];
    v = v > 0.f ? v : NEG_SLOPE * v;
    return __expf(v) * g_dd[d * DDS + 8 + h];
}

// fp16 packed accumulate: acc_{lo,hi} += w_h2 * u.{x,y}
__device__ __forceinline__ void acc_h2(__half2& lo, __half2& hi,
                                       uint2 u, unsigned wbits) {
    __half2 w = *(__half2*)&wbits;
    lo = __hfma2(w, *(__half2*)&u.x, lo);
    hi = __hfma2(w, *(__half2*)&u.y, hi);
}

// ---------------- kernel 3: scatter, 2 edges/warp, fp16 HFMA2 accumulation ---
__global__ __launch_bounds__(256)
void scatter_kernel(const int* __restrict__ ei,
                    float* __restrict__ out, int E, int Etot) {
    const int warp = threadIdx.x >> 5;
    const int lane = threadIdx.x & 31;
    const int e0 = (blockIdx.x * 8 + warp) * 2;
    const int e1 = e0 + 1;
    const bool v0 = (e0 < Etot);
    const bool v1 = (e1 < Etot);
    const int ec0 = v0 ? e0 : 0;
    const int ec1 = v1 ? e1 : 0;

    int s0, d0, s1, d1;
    if (ec0 < E) { s0 = ei[ec0]; d0 = ei[E + ec0]; } else { s0 = ec0 - E; d0 = s0; }
    if (ec1 < E) { s1 = ei[ec1]; d1 = ei[E + ec1]; } else { s1 = ec1 - E; d1 = s1; }

    // lanes 0..4 -> edge0 weights; lanes 8..12 -> edge1 weights.
    // Convert to broadcast half2 BEFORE the shuffle (shuffle moves the bits).
    float wv = 0.f;
    if (lane < Hh)                       wv = edge_w(s0, d0, lane);
    else if (lane >= 8 && lane < 8 + Hh) wv = edge_w(s1, d1, lane - 8);
    __half2 wh = __float2half2_rn(wv);
    unsigned wb = *(unsigned*)&wh;

    unsigned w0 = __shfl_sync(0xffffffffu, wb, 0);
    unsigned w1 = __shfl_sync(0xffffffffu, wb, 1);
    unsigned w2 = __shfl_sync(0xffffffffu, wb, 2);
    unsigned w3 = __shfl_sync(0xffffffffu, wb, 3);
    unsigned w4 = __shfl_sync(0xffffffffu, wb, 4);
    unsigned x0 = __shfl_sync(0xffffffffu, wb, 8);
    unsigned x1 = __shfl_sync(0xffffffffu, wb, 9);
    unsigned x2 = __shfl_sync(0xffffffffu, wb, 10);
    unsigned x3 = __shfl_sync(0xffffffffu, wb, 11);
    unsigned x4 = __shfl_sync(0xffffffffu, wb, 12);

    const uint2* hp0 = (const uint2*)(g_h + (size_t)s0 * HC) + lane;
    const uint2* hp1 = (const uint2*)(g_h + (size_t)s1 * HC) + lane;
    uint2 a0 = hp0[0 * 32], a1 = hp0[1 * 32], a2 = hp0[2 * 32],
          a3 = hp0[3 * 32], a4 = hp0[4 * 32];
    uint2 b0 = hp1[0 * 32], b1 = hp1[1 * 32], b2 = hp1[2 * 32],
          b3 = hp1[3 * 32], b4 = hp1[4 * 32];

    __half2 zero = __float2half2_rn(0.f);
    __half2 aLo = zero, aHi = zero, bLo = zero, bHi = zero;
    acc_h2(aLo, aHi, a0, w0); acc_h2(bLo, bHi, b0, x0);
    acc_h2(aLo, aHi, a1, w1); acc_h2(bLo, bHi, b1, x1);
    acc_h2(aLo, aHi, a2, w2); acc_h2(bLo, bHi, b2, x2);
    acc_h2(aLo, aHi, a3, w3); acc_h2(bLo, bHi, b3, x3);
    acc_h2(aLo, aHi, a4, w4); acc_h2(bLo, bHi, b4, x4);

    if (v0) {
        float2 lo = __half22float2(aLo);
        float2 hi = __half22float2(aHi);
        float* op = out + (size_t)d0 * Cn + lane * 4;
        asm volatile("red.global.add.v4.f32 [%0], {%1, %2, %3, %4};"
                     :: "l"(op), "f"(lo.x), "f"(lo.y), "f"(hi.x), "f"(hi.y)
                     : "memory");
    }
    if (v1) {
        float2 lo = __half22float2(bLo);
        float2 hi = __half22float2(bHi);
        float* op = out + (size_t)d1 * Cn + lane * 4;
        asm volatile("red.global.add.v4.f32 [%0], {%1, %2, %3, %4};"
                     :: "l"(op), "f"(lo.x), "f"(lo.y), "f"(hi.x), "f"(hi.y)
                     : "memory");
    }
}

// ---------------- launch -------------------------------------------------------
extern "C" void kernel_launch(void* const* d_in, const int* in_sizes, int n_in,
                              void* d_out, int out_size) {
    const float* features = (const float*)d_in[0];
    const float* W        = (const float*)d_in[1];
    const float* att_src  = (const float*)d_in[2];
    const float* att_dst  = (const float*)d_in[3];
    const float* bias     = (const float*)d_in[4];
    const int*   ei       = (const int*)d_in[5];
    float*       out      = (float*)d_out;

    const int Nn   = in_sizes[0] / Cn;   // 20000
    const int E    = in_sizes[5] / 2;    // 320000
    const int Etot = E + Nn;             // 340000

    // 0) prep: out = features + bias, fp16 converts, denom zero (vectorized)
    {
        int work = Nn * (Cn / 4);        // 640000, covers all ranges
        prep_kernel<<<(work + 255) / 256, 256>>>((const float4*)features, W,
                                                 (const float4*)bias,
                                                 (float4*)out, Nn);
    }

    // 1) GEMM (fp16 TC, un-chunked K) + fused logits (adst -> g_dd)
    {
        cudaFuncSetAttribute(gemm_tc_kernel,
                             cudaFuncAttributeMaxDynamicSharedMemorySize, SMEM_DYN);
        dim3 grid(Hh, (Nn + TBM - 1) / TBM);   // (5, 313)
        gemm_tc_kernel<<<grid, 256, SMEM_DYN>>>(att_src, att_dst, Nn);
    }

    // 2) softmax denominators (vectorized loads + v4 atomics)
    denom_kernel<<<(Etot + 255) / 256, 256>>>(ei, E, Etot);

    // 2.5) reciprocal denominators, packed next to adst
    rdenom_kernel<<<(Nn * Hh + 255) / 256, 256>>>(Nn * Hh);

    // 3) scatter: 2 edges per warp, fp16 HFMA2 accumulation
    scatter_kernel<<<(Etot + 15) / 16, 256>>>(ei, out, E, Etot);
}